// round 7
// baseline (speedup 1.0000x reference)
#include <cuda_runtime.h>
#include <cuda_fp16.h>
#include <cuda_bf16.h>
#include <cstdint>

#define N_NODES 100000
#define N_FEATS 128
#define MAX_DEG 64   // Poisson(6.4): P(deg >= 64) < 1e-30 over 100k nodes

__device__ __half g_Yh[(size_t)N_NODES * N_FEATS];   // 25.6 MB, fp16
__device__ int g_cnt[N_NODES];                        // zero-init at load
__device__ int g_bucket[(size_t)N_NODES * MAX_DEG];   // 25.6 MB

// ---------------------------------------------------------------------------
// Kernel 1: Y = feature @ W via tf32 mma.sync.m16n8k8, fp16 output
// block = 512 threads (16 warps: 4 along M x 4 along N), tile 128x128
// ---------------------------------------------------------------------------
#define FSH_STRIDE 132
#define WSH_STRIDE 136

__device__ __forceinline__ uint32_t f2tf32(float x) {
    uint32_t r;
    asm("cvt.rna.tf32.f32 %0, %1;" : "=r"(r) : "f"(x));
    return r;
}

__global__ void __launch_bounds__(512, 1)
gemm_tf32_kernel(const float* __restrict__ F,
                 const float* __restrict__ W,
                 int n_rows) {
    extern __shared__ uint32_t sh[];
    uint32_t* Fsh = sh;                          // [128][FSH_STRIDE]
    uint32_t* Wsh = sh + 128 * FSH_STRIDE;       // [128][WSH_STRIDE] (k-major)

    const int tid  = threadIdx.x;
    const int lane = tid & 31;
    const int wid  = tid >> 5;
    const int warp_m = wid >> 2;
    const int warp_n = wid & 3;

    const int row0 = blockIdx.x * 128;

    const float4* W4 = reinterpret_cast<const float4*>(W);
    #pragma unroll
    for (int i = tid; i < 128 * 32; i += 512) {
        int k = i >> 5, j = i & 31;
        float4 w = W4[i];
        uint32_t* p = Wsh + k * WSH_STRIDE + j * 4;
        p[0] = f2tf32(w.x); p[1] = f2tf32(w.y); p[2] = f2tf32(w.z); p[3] = f2tf32(w.w);
    }

    const float4* F4 = reinterpret_cast<const float4*>(F);
    #pragma unroll
    for (int i = tid; i < 128 * 32; i += 512) {
        int r = i >> 5, j = i & 31;
        float4 f = (row0 + r < n_rows) ? F4[(size_t)(row0 + r) * 32 + j]
                                       : make_float4(0.f, 0.f, 0.f, 0.f);
        uint32_t* p = Fsh + r * FSH_STRIDE + j * 4;
        p[0] = f2tf32(f.x); p[1] = f2tf32(f.y); p[2] = f2tf32(f.z); p[3] = f2tf32(f.w);
    }
    __syncthreads();

    float acc[2][4][4];
    #pragma unroll
    for (int am = 0; am < 2; am++)
        #pragma unroll
        for (int nb = 0; nb < 4; nb++)
            #pragma unroll
            for (int c = 0; c < 4; c++)
                acc[am][nb][c] = 0.f;

    const int gid  = lane >> 2;
    const int tid4 = lane & 3;

    #pragma unroll
    for (int ks = 0; ks < 16; ks++) {
        uint32_t a[2][4];
        const int ac = ks * 8 + tid4;
        #pragma unroll
        for (int am = 0; am < 2; am++) {
            int r = warp_m * 32 + am * 16 + gid;
            const uint32_t* base = Fsh + r * FSH_STRIDE;
            a[am][0] = base[ac];
            a[am][1] = base[8 * FSH_STRIDE + ac];
            a[am][2] = base[ac + 4];
            a[am][3] = base[8 * FSH_STRIDE + ac + 4];
        }
        uint32_t bf[4][2];
        const int br = ks * 8 + tid4;
        #pragma unroll
        for (int nb = 0; nb < 4; nb++) {
            int cidx = warp_n * 32 + nb * 8 + gid;
            bf[nb][0] = Wsh[br * WSH_STRIDE + cidx];
            bf[nb][1] = Wsh[(br + 4) * WSH_STRIDE + cidx];
        }
        #pragma unroll
        for (int am = 0; am < 2; am++)
            #pragma unroll
            for (int nb = 0; nb < 4; nb++) {
                asm volatile(
                    "mma.sync.aligned.m16n8k8.row.col.f32.tf32.tf32.f32 "
                    "{%0,%1,%2,%3}, {%4,%5,%6,%7}, {%8,%9}, {%0,%1,%2,%3};"
                    : "+f"(acc[am][nb][0]), "+f"(acc[am][nb][1]),
                      "+f"(acc[am][nb][2]), "+f"(acc[am][nb][3])
                    : "r"(a[am][0]), "r"(a[am][1]), "r"(a[am][2]), "r"(a[am][3]),
                      "r"(bf[nb][0]), "r"(bf[nb][1]));
            }
    }

    // Write Y as fp16 (half2 per (c0,c1)/(c2,c3) pair)
    #pragma unroll
    for (int am = 0; am < 2; am++) {
        int r_lo = row0 + warp_m * 32 + am * 16 + gid;
        int r_hi = r_lo + 8;
        #pragma unroll
        for (int nb = 0; nb < 4; nb++) {
            int col = warp_n * 32 + nb * 8 + 2 * tid4;
            if (r_lo < n_rows) {
                __half2 h = __floats2half2_rn(acc[am][nb][0], acc[am][nb][1]);
                *reinterpret_cast<__half2*>(g_Yh + (size_t)r_lo * 128 + col) = h;
            }
            if (r_hi < n_rows) {
                __half2 h = __floats2half2_rn(acc[am][nb][2], acc[am][nb][3]);
                *reinterpret_cast<__half2*>(g_Yh + (size_t)r_hi * 128 + col) = h;
            }
        }
    }
}

// ---------------------------------------------------------------------------
// Kernel 2: bucket edges by destination
// ---------------------------------------------------------------------------
__global__ void fill_buckets_kernel(const int* __restrict__ ei, int n_edges) {
    int e = blockIdx.x * blockDim.x + threadIdx.x;
    if (e >= n_edges) return;
    int s = ei[e];
    int d = ei[n_edges + e];
    int pos = atomicAdd(&g_cnt[d], 1);
    if (pos < MAX_DEG) g_bucket[(size_t)d * MAX_DEG + pos] = s;
}

// ---------------------------------------------------------------------------
// Kernel 3: gather-reduce — out[n] = b + sum_{e: dst=n} Yh[src(e)]
// one warp per node; TWO edges per step (16 lanes each, LDG.128 = 8 halfs)
// fp32 accumulate, shfl_xor(16) combine. Re-zeroes g_cnt for next call.
// ---------------------------------------------------------------------------
__device__ __forceinline__ void accum8(float acc[8], uint4 v) {
    float2 f;
    f = __half22float2(*reinterpret_cast<__half2*>(&v.x)); acc[0] += f.x; acc[1] += f.y;
    f = __half22float2(*reinterpret_cast<__half2*>(&v.y)); acc[2] += f.x; acc[3] += f.y;
    f = __half22float2(*reinterpret_cast<__half2*>(&v.z)); acc[4] += f.x; acc[5] += f.y;
    f = __half22float2(*reinterpret_cast<__half2*>(&v.w)); acc[6] += f.x; acc[7] += f.y;
}

__global__ void gather_kernel(const float* __restrict__ b,
                              float* __restrict__ out,
                              int n_nodes) {
    const int node = (int)(((size_t)blockIdx.x * blockDim.x + threadIdx.x) >> 5);
    const int lane = threadIdx.x & 31;
    if (node >= n_nodes) return;

    const int cnt = g_cnt[node];
    if (lane == 0) g_cnt[node] = 0;   // reset for next kernel_launch call

    const int hid = lane >> 4;        // 0 or 1: which edge of the pair
    const int j   = lane & 15;        // 16-byte chunk within row (cols 8j..8j+7)

    const char* yb = reinterpret_cast<const char*>(g_Yh);
    const int2* bk2 = reinterpret_cast<const int2*>(g_bucket + (size_t)node * MAX_DEG);

    float acc[8] = {0.f, 0.f, 0.f, 0.f, 0.f, 0.f, 0.f, 0.f};
    const uint32_t joff = (uint32_t)j * 16u;

    for (int base = 0; base < cnt; base += 4) {
        int2 p0 = __ldg(&bk2[(base >> 1) + 0]);   // edges base, base+1
        int2 p1 = __ldg(&bk2[(base >> 1) + 1]);   // edges base+2, base+3
        int s0 = hid ? p0.y : p0.x;
        int s1 = hid ? p1.y : p1.x;

        uint4 v0 = make_uint4(0, 0, 0, 0);
        uint4 v1 = make_uint4(0, 0, 0, 0);
        if (base + hid < cnt)
            v0 = __ldg(reinterpret_cast<const uint4*>(yb + ((uint32_t)s0 * 256u + joff)));
        if (base + 2 + hid < cnt)
            v1 = __ldg(reinterpret_cast<const uint4*>(yb + ((uint32_t)s1 * 256u + joff)));

        accum8(acc, v0);
        accum8(acc, v1);
    }

    // combine the two half-warps (each holds partial sums of the same columns)
    #pragma unroll
    for (int k = 0; k < 8; k++)
        acc[k] += __shfl_xor_sync(0xffffffffu, acc[k], 16);

    // bias + store: lane writes 4 floats at col = 8j + 4*hid
    float4 bb = __ldg(&reinterpret_cast<const float4*>(b)[2 * j + hid]);
    float4 o;
    o.x = acc[hid * 4 + 0] + bb.x;
    o.y = acc[hid * 4 + 1] + bb.y;
    o.z = acc[hid * 4 + 2] + bb.z;
    o.w = acc[hid * 4 + 3] + bb.w;
    *reinterpret_cast<float4*>(out + (size_t)node * 128 + j * 8 + hid * 4) = o;
}

// ---------------------------------------------------------------------------
extern "C" void kernel_launch(void* const* d_in, const int* in_sizes, int n_in,
                              void* d_out, int out_size) {
    const float* feature = (const float*)d_in[0];
    const int*   ei      = (const int*)d_in[1];
    const float* W       = (const float*)d_in[2];
    const float* b       = (const float*)d_in[3];
    float*       out     = (float*)d_out;

    const int n_nodes = in_sizes[0] / N_FEATS;
    const int n_edges = in_sizes[1] / 2;

    // Bucket build (g_cnt is zero: loader-init on first call, gather re-zeroes after)
    fill_buckets_kernel<<<(n_edges + 255) / 256, 256>>>(ei, n_edges);

    // GEMM: Y = feature @ W  (tf32 tensor path, fp16 output)
    const int smem_bytes = (128 * FSH_STRIDE + 128 * WSH_STRIDE) * (int)sizeof(uint32_t);
    cudaFuncSetAttribute(gemm_tf32_kernel,
                         cudaFuncAttributeMaxDynamicSharedMemorySize, smem_bytes);
    int gemm_blocks = (n_nodes + 127) / 128;
    gemm_tf32_kernel<<<gemm_blocks, 512, smem_bytes>>>(feature, W, n_nodes);

    // Gather-reduce with fused bias (one warp per node, 2 edges per step)
    int warps_per_block = 256 / 32;
    int gat_blocks = (n_nodes + warps_per_block - 1) / warps_per_block;
    gather_kernel<<<gat_blocks, 256>>>(b, out, n_nodes);
}

// round 8
// speedup vs baseline: 1.0108x; 1.0108x over previous
#include <cuda_runtime.h>
#include <cuda_fp16.h>
#include <cuda_bf16.h>
#include <cstdint>

#define N_NODES 100000
#define N_FEATS 128
#define MAX_DEG 64   // Poisson(6.4): P(deg >= 64) < 1e-30 over 100k nodes

__device__ __half g_Yh[(size_t)N_NODES * N_FEATS];   // 25.6 MB, fp16
__device__ int g_cnt[N_NODES];                        // zero-init at load; gather re-zeroes
__device__ int g_bucket[(size_t)N_NODES * MAX_DEG];   // 25.6 MB

// ---------------------------------------------------------------------------
// Kernel 1: Y = feature @ W via tf32 mma.sync.m16n8k8, fp16 output
// block = 512 threads (16 warps: 4 along M x 4 along N), tile 128x128
// ---------------------------------------------------------------------------
#define FSH_STRIDE 132
#define WSH_STRIDE 136

__device__ __forceinline__ uint32_t f2tf32(float x) {
    uint32_t r;
    asm("cvt.rna.tf32.f32 %0, %1;" : "=r"(r) : "f"(x));
    return r;
}

__global__ void __launch_bounds__(512, 1)
gemm_tf32_kernel(const float* __restrict__ F,
                 const float* __restrict__ W,
                 int n_rows) {
    extern __shared__ uint32_t sh[];
    uint32_t* Fsh = sh;                          // [128][FSH_STRIDE]
    uint32_t* Wsh = sh + 128 * FSH_STRIDE;       // [128][WSH_STRIDE] (k-major)

    const int tid  = threadIdx.x;
    const int lane = tid & 31;
    const int wid  = tid >> 5;
    const int warp_m = wid >> 2;
    const int warp_n = wid & 3;

    const int row0 = blockIdx.x * 128;

    const float4* W4 = reinterpret_cast<const float4*>(W);
    #pragma unroll
    for (int i = tid; i < 128 * 32; i += 512) {
        int k = i >> 5, j = i & 31;
        float4 w = W4[i];
        uint32_t* p = Wsh + k * WSH_STRIDE + j * 4;
        p[0] = f2tf32(w.x); p[1] = f2tf32(w.y); p[2] = f2tf32(w.z); p[3] = f2tf32(w.w);
    }

    const float4* F4 = reinterpret_cast<const float4*>(F);
    #pragma unroll
    for (int i = tid; i < 128 * 32; i += 512) {
        int r = i >> 5, j = i & 31;
        float4 f = (row0 + r < n_rows) ? F4[(size_t)(row0 + r) * 32 + j]
                                       : make_float4(0.f, 0.f, 0.f, 0.f);
        uint32_t* p = Fsh + r * FSH_STRIDE + j * 4;
        p[0] = f2tf32(f.x); p[1] = f2tf32(f.y); p[2] = f2tf32(f.z); p[3] = f2tf32(f.w);
    }
    __syncthreads();

    float acc[2][4][4];
    #pragma unroll
    for (int am = 0; am < 2; am++)
        #pragma unroll
        for (int nb = 0; nb < 4; nb++)
            #pragma unroll
            for (int c = 0; c < 4; c++)
                acc[am][nb][c] = 0.f;

    const int gid  = lane >> 2;
    const int tid4 = lane & 3;

    #pragma unroll
    for (int ks = 0; ks < 16; ks++) {
        uint32_t a[2][4];
        const int ac = ks * 8 + tid4;
        #pragma unroll
        for (int am = 0; am < 2; am++) {
            int r = warp_m * 32 + am * 16 + gid;
            const uint32_t* base = Fsh + r * FSH_STRIDE;
            a[am][0] = base[ac];
            a[am][1] = base[8 * FSH_STRIDE + ac];
            a[am][2] = base[ac + 4];
            a[am][3] = base[8 * FSH_STRIDE + ac + 4];
        }
        uint32_t bf[4][2];
        const int br = ks * 8 + tid4;
        #pragma unroll
        for (int nb = 0; nb < 4; nb++) {
            int cidx = warp_n * 32 + nb * 8 + gid;
            bf[nb][0] = Wsh[br * WSH_STRIDE + cidx];
            bf[nb][1] = Wsh[(br + 4) * WSH_STRIDE + cidx];
        }
        #pragma unroll
        for (int am = 0; am < 2; am++)
            #pragma unroll
            for (int nb = 0; nb < 4; nb++) {
                asm volatile(
                    "mma.sync.aligned.m16n8k8.row.col.f32.tf32.tf32.f32 "
                    "{%0,%1,%2,%3}, {%4,%5,%6,%7}, {%8,%9}, {%0,%1,%2,%3};"
                    : "+f"(acc[am][nb][0]), "+f"(acc[am][nb][1]),
                      "+f"(acc[am][nb][2]), "+f"(acc[am][nb][3])
                    : "r"(a[am][0]), "r"(a[am][1]), "r"(a[am][2]), "r"(a[am][3]),
                      "r"(bf[nb][0]), "r"(bf[nb][1]));
            }
    }

    // Write Y as fp16
    #pragma unroll
    for (int am = 0; am < 2; am++) {
        int r_lo = row0 + warp_m * 32 + am * 16 + gid;
        int r_hi = r_lo + 8;
        #pragma unroll
        for (int nb = 0; nb < 4; nb++) {
            int col = warp_n * 32 + nb * 8 + 2 * tid4;
            if (r_lo < n_rows) {
                __half2 h = __floats2half2_rn(acc[am][nb][0], acc[am][nb][1]);
                *reinterpret_cast<__half2*>(g_Yh + (size_t)r_lo * 128 + col) = h;
            }
            if (r_hi < n_rows) {
                __half2 h = __floats2half2_rn(acc[am][nb][2], acc[am][nb][3]);
                *reinterpret_cast<__half2*>(g_Yh + (size_t)r_hi * 128 + col) = h;
            }
        }
    }
}

// ---------------------------------------------------------------------------
// Kernel 2: bucket edges by destination
// ---------------------------------------------------------------------------
__global__ void fill_buckets_kernel(const int* __restrict__ ei, int n_edges) {
    int e = blockIdx.x * blockDim.x + threadIdx.x;
    if (e >= n_edges) return;
    int s = ei[e];
    int d = ei[n_edges + e];
    int pos = atomicAdd(&g_cnt[d], 1);
    if (pos < MAX_DEG) g_bucket[(size_t)d * MAX_DEG + pos] = s;
}

// ---------------------------------------------------------------------------
// Kernel 3: gather-reduce — out[n] = b + sum_{e: dst=n} Yh[src(e)]
// one warp per node; half-warp per edge (16 lanes x LDG.128 = one 256B row);
// 16 edges per iteration -> 8 predicated loads in flight per lane (MLP=8).
// fp32 accumulate, shfl_xor(16) combine. Re-zeroes g_cnt for next call.
// ---------------------------------------------------------------------------
__device__ __forceinline__ void accum8(float acc[8], uint4 v) {
    float2 f;
    f = __half22float2(*reinterpret_cast<__half2*>(&v.x)); acc[0] += f.x; acc[1] += f.y;
    f = __half22float2(*reinterpret_cast<__half2*>(&v.y)); acc[2] += f.x; acc[3] += f.y;
    f = __half22float2(*reinterpret_cast<__half2*>(&v.z)); acc[4] += f.x; acc[5] += f.y;
    f = __half22float2(*reinterpret_cast<__half2*>(&v.w)); acc[6] += f.x; acc[7] += f.y;
}

__global__ void gather_kernel(const float* __restrict__ b,
                              float* __restrict__ out,
                              int n_nodes) {
    const int node = (int)(((size_t)blockIdx.x * blockDim.x + threadIdx.x) >> 5);
    const int lane = threadIdx.x & 31;
    if (node >= n_nodes) return;

    const int cnt = g_cnt[node];
    if (lane == 0) g_cnt[node] = 0;   // reset for next kernel_launch call

    const int hid = lane >> 4;        // which edge of each pair
    const int j   = lane & 15;        // 16-byte chunk within the 256B row
    const uint32_t joff = (uint32_t)j * 16u;

    const char* yb = reinterpret_cast<const char*>(g_Yh);
    const int*  bk = g_bucket + (size_t)node * MAX_DEG;

    float acc[8] = {0.f, 0.f, 0.f, 0.f, 0.f, 0.f, 0.f, 0.f};

    for (int base = 0; base < cnt; base += 16) {
        // 16 bucket indices via 4 broadcast int4 loads
        const int4* bk4 = reinterpret_cast<const int4*>(bk + base);
        int4 q0 = __ldg(&bk4[0]);
        int4 q1 = __ldg(&bk4[1]);
        int4 q2 = __ldg(&bk4[2]);
        int4 q3 = __ldg(&bk4[3]);

        int s[8];
        s[0] = hid ? q0.y : q0.x;   // edges base+0 / base+1
        s[1] = hid ? q0.w : q0.z;   // edges base+2 / base+3
        s[2] = hid ? q1.y : q1.x;
        s[3] = hid ? q1.w : q1.z;
        s[4] = hid ? q2.y : q2.x;
        s[5] = hid ? q2.w : q2.z;
        s[6] = hid ? q3.y : q3.x;
        s[7] = hid ? q3.w : q3.z;

        uint4 v[8];
        #pragma unroll
        for (int k = 0; k < 8; k++) {
            v[k] = (base + 2 * k + hid < cnt)
                 ? __ldg(reinterpret_cast<const uint4*>(yb + ((uint32_t)s[k] * 256u + joff)))
                 : make_uint4(0, 0, 0, 0);
        }
        #pragma unroll
        for (int k = 0; k < 8; k++)
            accum8(acc, v[k]);
    }

    // combine the two half-warps (same columns, disjoint edge subsets)
    #pragma unroll
    for (int k = 0; k < 8; k++)
        acc[k] += __shfl_xor_sync(0xffffffffu, acc[k], 16);

    // bias + store: lane writes 4 floats at col = 8j + 4*hid
    float4 bb = __ldg(&reinterpret_cast<const float4*>(b)[2 * j + hid]);
    float4 o;
    o.x = acc[hid * 4 + 0] + bb.x;
    o.y = acc[hid * 4 + 1] + bb.y;
    o.z = acc[hid * 4 + 2] + bb.z;
    o.w = acc[hid * 4 + 3] + bb.w;
    *reinterpret_cast<float4*>(out + (size_t)node * 128 + j * 8 + hid * 4) = o;
}

// ---------------------------------------------------------------------------
extern "C" void kernel_launch(void* const* d_in, const int* in_sizes, int n_in,
                              void* d_out, int out_size) {
    const float* feature = (const float*)d_in[0];
    const int*   ei      = (const int*)d_in[1];
    const float* W       = (const float*)d_in[2];
    const float* b       = (const float*)d_in[3];
    float*       out     = (float*)d_out;

    const int n_nodes = in_sizes[0] / N_FEATS;
    const int n_edges = in_sizes[1] / 2;

    // Bucket build (g_cnt zero: loader-init first call, gather re-zeroes after)
    fill_buckets_kernel<<<(n_edges + 255) / 256, 256>>>(ei, n_edges);

    // GEMM: Y = feature @ W  (tf32 tensor path, fp16 output)
    const int smem_bytes = (128 * FSH_STRIDE + 128 * WSH_STRIDE) * (int)sizeof(uint32_t);
    cudaFuncSetAttribute(gemm_tf32_kernel,
                         cudaFuncAttributeMaxDynamicSharedMemorySize, smem_bytes);
    int gemm_blocks = (n_nodes + 127) / 128;
    gemm_tf32_kernel<<<gemm_blocks, 512, smem_bytes>>>(feature, W, n_nodes);

    // Gather-reduce with fused bias (one warp per node, 16 edges/iter, MLP=8)
    int warps_per_block = 256 / 32;
    int gat_blocks = (n_nodes + warps_per_block - 1) / warps_per_block;
    gather_kernel<<<gat_blocks, 256>>>(b, out, n_nodes);
}

// round 9
// speedup vs baseline: 2.1273x; 2.1046x over previous
#include <cuda_runtime.h>
#include <cuda_fp16.h>
#include <cuda_bf16.h>
#include <cstdint>

#define N_NODES 100000
#define N_FEATS 128
#define MAX_DEG 64   // Poisson(6.4): P(deg >= 64) < 1e-30 over 100k nodes

__device__ __half g_Yh[(size_t)N_NODES * N_FEATS];   // 25.6 MB, fp16
__device__ int g_cnt[N_NODES];
__device__ int g_bucket[(size_t)N_NODES * MAX_DEG];   // 25.6 MB

// ---------------------------------------------------------------------------
// Kernel 1: Y = feature @ W via tf32 mma.sync.m16n8k8, fp16 output
// block = 512 threads (16 warps: 4 along M x 4 along N), tile 128x128
// ---------------------------------------------------------------------------
#define FSH_STRIDE 132
#define WSH_STRIDE 136

__device__ __forceinline__ uint32_t f2tf32(float x) {
    uint32_t r;
    asm("cvt.rna.tf32.f32 %0, %1;" : "=r"(r) : "f"(x));
    return r;
}

__global__ void __launch_bounds__(512, 1)
gemm_tf32_kernel(const float* __restrict__ F,
                 const float* __restrict__ W,
                 int n_rows) {
    extern __shared__ uint32_t sh[];
    uint32_t* Fsh = sh;                          // [128][FSH_STRIDE]
    uint32_t* Wsh = sh + 128 * FSH_STRIDE;       // [128][WSH_STRIDE] (k-major)

    const int tid  = threadIdx.x;
    const int lane = tid & 31;
    const int wid  = tid >> 5;
    const int warp_m = wid >> 2;
    const int warp_n = wid & 3;

    const int row0 = blockIdx.x * 128;

    const float4* W4 = reinterpret_cast<const float4*>(W);
    #pragma unroll
    for (int i = tid; i < 128 * 32; i += 512) {
        int k = i >> 5, j = i & 31;
        float4 w = W4[i];
        uint32_t* p = Wsh + k * WSH_STRIDE + j * 4;
        p[0] = f2tf32(w.x); p[1] = f2tf32(w.y); p[2] = f2tf32(w.z); p[3] = f2tf32(w.w);
    }

    const float4* F4 = reinterpret_cast<const float4*>(F);
    #pragma unroll
    for (int i = tid; i < 128 * 32; i += 512) {
        int r = i >> 5, j = i & 31;
        float4 f = (row0 + r < n_rows) ? F4[(size_t)(row0 + r) * 32 + j]
                                       : make_float4(0.f, 0.f, 0.f, 0.f);
        uint32_t* p = Fsh + r * FSH_STRIDE + j * 4;
        p[0] = f2tf32(f.x); p[1] = f2tf32(f.y); p[2] = f2tf32(f.z); p[3] = f2tf32(f.w);
    }
    __syncthreads();

    float acc[2][4][4];
    #pragma unroll
    for (int am = 0; am < 2; am++)
        #pragma unroll
        for (int nb = 0; nb < 4; nb++)
            #pragma unroll
            for (int c = 0; c < 4; c++)
                acc[am][nb][c] = 0.f;

    const int gid  = lane >> 2;
    const int tid4 = lane & 3;

    #pragma unroll
    for (int ks = 0; ks < 16; ks++) {
        uint32_t a[2][4];
        const int ac = ks * 8 + tid4;
        #pragma unroll
        for (int am = 0; am < 2; am++) {
            int r = warp_m * 32 + am * 16 + gid;
            const uint32_t* base = Fsh + r * FSH_STRIDE;
            a[am][0] = base[ac];
            a[am][1] = base[8 * FSH_STRIDE + ac];
            a[am][2] = base[ac + 4];
            a[am][3] = base[8 * FSH_STRIDE + ac + 4];
        }
        uint32_t bf[4][2];
        const int br = ks * 8 + tid4;
        #pragma unroll
        for (int nb = 0; nb < 4; nb++) {
            int cidx = warp_n * 32 + nb * 8 + gid;
            bf[nb][0] = Wsh[br * WSH_STRIDE + cidx];
            bf[nb][1] = Wsh[(br + 4) * WSH_STRIDE + cidx];
        }
        #pragma unroll
        for (int am = 0; am < 2; am++)
            #pragma unroll
            for (int nb = 0; nb < 4; nb++) {
                asm volatile(
                    "mma.sync.aligned.m16n8k8.row.col.f32.tf32.tf32.f32 "
                    "{%0,%1,%2,%3}, {%4,%5,%6,%7}, {%8,%9}, {%0,%1,%2,%3};"
                    : "+f"(acc[am][nb][0]), "+f"(acc[am][nb][1]),
                      "+f"(acc[am][nb][2]), "+f"(acc[am][nb][3])
                    : "r"(a[am][0]), "r"(a[am][1]), "r"(a[am][2]), "r"(a[am][3]),
                      "r"(bf[nb][0]), "r"(bf[nb][1]));
            }
    }

    // Write Y as fp16
    #pragma unroll
    for (int am = 0; am < 2; am++) {
        int r_lo = row0 + warp_m * 32 + am * 16 + gid;
        int r_hi = r_lo + 8;
        #pragma unroll
        for (int nb = 0; nb < 4; nb++) {
            int col = warp_n * 32 + nb * 8 + 2 * tid4;
            if (r_lo < n_rows) {
                __half2 h = __floats2half2_rn(acc[am][nb][0], acc[am][nb][1]);
                *reinterpret_cast<__half2*>(g_Yh + (size_t)r_lo * 128 + col) = h;
            }
            if (r_hi < n_rows) {
                __half2 h = __floats2half2_rn(acc[am][nb][2], acc[am][nb][3]);
                *reinterpret_cast<__half2*>(g_Yh + (size_t)r_hi * 128 + col) = h;
            }
        }
    }
}

// ---------------------------------------------------------------------------
// Kernel 2: zero per-node counters
// ---------------------------------------------------------------------------
__global__ void zero_cnt_kernel(int n_nodes) {
    int i = blockIdx.x * blockDim.x + threadIdx.x;
    if (i < n_nodes) g_cnt[i] = 0;
}

// ---------------------------------------------------------------------------
// Kernel 3: bucket edges by destination
// ---------------------------------------------------------------------------
__global__ void fill_buckets_kernel(const int* __restrict__ ei, int n_edges) {
    int e = blockIdx.x * blockDim.x + threadIdx.x;
    if (e >= n_edges) return;
    int s = ei[e];
    int d = ei[n_edges + e];
    int pos = atomicAdd(&g_cnt[d], 1);
    if (pos < MAX_DEG) g_bucket[(size_t)d * MAX_DEG + pos] = s;
}

// ---------------------------------------------------------------------------
// Kernel 4: gather-reduce — out[n] = b + sum_{e: dst=n} Yh[src(e)]
// R6 structure: one warp per node, FULL warp per edge (lane owns 4 cols,
// LDG.64 = 4 halfs), 8 edges per iteration fully predicated (MLP=8).
// ---------------------------------------------------------------------------
__global__ void gather_kernel(const float* __restrict__ b,
                              float* __restrict__ out,
                              int n_nodes) {
    const int node = (int)(((size_t)blockIdx.x * blockDim.x + threadIdx.x) >> 5);
    const int lane = threadIdx.x & 31;
    if (node >= n_nodes) return;

    int cnt = g_cnt[node];
    if (cnt > MAX_DEG) cnt = MAX_DEG;

    const int4* bk4 = reinterpret_cast<const int4*>(g_bucket + (size_t)node * MAX_DEG);
    const char* yb = reinterpret_cast<const char*>(g_Yh);
    const uint32_t loff = (uint32_t)lane * 8u;   // lane owns cols [4*lane, 4*lane+4)

    float4 acc = __ldg(&reinterpret_cast<const float4*>(b)[lane]);

    for (int base = 0; base < cnt; base += 8) {
        // broadcast bucket indices (two int4 = 8 srcs)
        int4 p0 = __ldg(&bk4[(base >> 2) + 0]);
        int4 p1 = __ldg(&bk4[(base >> 2) + 1]);
        int s[8] = {p0.x, p0.y, p0.z, p0.w, p1.x, p1.y, p1.z, p1.w};

        uint2 v[8];
        #pragma unroll
        for (int j = 0; j < 8; j++) {
            v[j] = (base + j < cnt)
                 ? __ldg(reinterpret_cast<const uint2*>(yb + ((uint32_t)s[j] * 256u + loff)))
                 : make_uint2(0, 0);
        }
        #pragma unroll
        for (int j = 0; j < 8; j++) {
            float2 f0 = __half22float2(*reinterpret_cast<__half2*>(&v[j].x));
            float2 f1 = __half22float2(*reinterpret_cast<__half2*>(&v[j].y));
            acc.x += f0.x; acc.y += f0.y; acc.z += f1.x; acc.w += f1.y;
        }
    }

    reinterpret_cast<float4*>(out + (size_t)node * 128)[lane] = acc;
}

// ---------------------------------------------------------------------------
extern "C" void kernel_launch(void* const* d_in, const int* in_sizes, int n_in,
                              void* d_out, int out_size) {
    const float* feature = (const float*)d_in[0];
    const int*   ei      = (const int*)d_in[1];
    const float* W       = (const float*)d_in[2];
    const float* b       = (const float*)d_in[3];
    float*       out     = (float*)d_out;

    const int n_nodes = in_sizes[0] / N_FEATS;
    const int n_edges = in_sizes[1] / 2;

    // Bucket build (independent of GEMM)
    zero_cnt_kernel<<<(n_nodes + 255) / 256, 256>>>(n_nodes);
    fill_buckets_kernel<<<(n_edges + 255) / 256, 256>>>(ei, n_edges);

    // GEMM: Y = feature @ W  (tf32 tensor path, fp16 output)
    const int smem_bytes = (128 * FSH_STRIDE + 128 * WSH_STRIDE) * (int)sizeof(uint32_t);
    cudaFuncSetAttribute(gemm_tf32_kernel,
                         cudaFuncAttributeMaxDynamicSharedMemorySize, smem_bytes);
    int gemm_blocks = (n_nodes + 127) / 128;
    gemm_tf32_kernel<<<gemm_blocks, 512, smem_bytes>>>(feature, W, n_nodes);

    // Gather-reduce with fused bias (one warp per node, 8 edges/iter, MLP=8)
    int warps_per_block = 256 / 32;
    int gat_blocks = (n_nodes + warps_per_block - 1) / warps_per_block;
    gather_kernel<<<gat_blocks, 256>>>(b, out, n_nodes);
}